// round 5
// baseline (speedup 1.0000x reference)
#include <cuda_runtime.h>
#include <cooperative_groups.h>
#include <math.h>
#include <stdint.h>

namespace cg = cooperative_groups;

#define NN      96
#define NSQ     9216
#define NOFF    13
#define NNZ     119808
#define SIDE    816
#define BORD    24
#define KCONST  6.683942601602444f   /* 2*pi/0.94 */
#define OUTSIDE 768
#define OUTPLANE (OUTSIDE*OUTSIDE)

// ---------------- scratch (static device globals; no allocation) ------------
__device__ float  g_hs[NSQ];
__device__ float  g_Eys[NSQ];
__device__ float  g_neff[NSQ];
__device__ float2 g_U0[NSQ];
__device__ float2 g_Uz[NSQ];
__device__ float  g_craw[NNZ];
__device__ float  g_kraw[NNZ];
__device__ float  g_m[NNZ];
__device__ float  g_ci[NNZ];

// ---------------- kernel 1: hs / Eys / U0 (8x8 pooling) ---------------------
__global__ __launch_bounds__(256) void prep_kernel(const float* __restrict__ h_paras,
                                                   const float* __restrict__ E0)
{
    int p = blockIdx.x * 256 + threadIdx.x;
    if (p >= NSQ) return;
    float h  = h_paras[p];
    float s  = 1.f / (1.f + expf(-h));
    float hs = s * 0.6f + 0.2f;            // H_MIN + sig*(H_MAX-H_MIN)
    g_hs[p]  = hs;
    g_Eys[p] = 1.0f + 0.1f * tanhf(hs);
    float coupl = 0.5f + 0.5f * (1.f / (1.f + expf(-hs)));

    int i = p / NN, j = p % NN;
    const float* base = E0 + (size_t)(BORD + 8 * i) * SIDE + (BORD + 8 * j);
    float sum = 0.f;
    #pragma unroll
    for (int pi = 0; pi < 8; pi++) {
        float4 a = *(const float4*)(base + pi * SIDE);
        float4 b = *(const float4*)(base + pi * SIDE + 4);
        sum += (a.x + a.y) + (a.z + a.w) + (b.x + b.y) + (b.z + b.w);
    }
    g_U0[p] = make_float2(sum * (1.f / 64.f) * coupl, 0.f);
}

// ---------------- kernel 2: fused 3-layer MLP (mode 0=neff, 1=c, 2=k) -------
// Block handles 128 rows; 256 threads; 8x8 register tiles; k in 4 chunks of 32.
__global__ __launch_bounds__(256) void mlp_kernel(int mode,
    const float* __restrict__ w1, const float* __restrict__ b1,
    const float* __restrict__ w2, const float* __restrict__ b2,
    const float* __restrict__ w3, const float* __restrict__ b3,
    const float* __restrict__ dis, const int* __restrict__ coo)
{
    __shared__ float h1s[32 * 128];
    __shared__ float w2s[32 * 128];
    __shared__ float xs[4 * 128];
    __shared__ float red[16 * 128];

    int tid  = threadIdx.x;
    int base = blockIdx.x * 128;

    if (tid < 128) {
        int e = base + tid;
        if (mode == 0) {
            xs[tid] = g_hs[e];
        } else {
            int r = coo[e];
            int c = coo[NNZ + e];
            xs[tid]       = g_hs[r];
            xs[128 + tid] = g_hs[c];
            xs[256 + tid] = dis[2 * e];
            xs[384 + tid] = dis[2 * e + 1];
        }
    }
    __syncthreads();

    int tx = tid & 15, ty = tid >> 4;
    float acc[8][8];
    #pragma unroll
    for (int i = 0; i < 8; i++)
        #pragma unroll
        for (int j = 0; j < 8; j++) acc[i][j] = 0.f;

    for (int kb = 0; kb < 4; kb++) {
        // fill h1 chunk (layer-1 + tanh) and w2 chunk
        #pragma unroll
        for (int it = 0; it < 16; it++) {
            int idx = tid + it * 256;           // 0..4095
            int kk  = idx >> 7;                 // 0..31
            int e   = idx & 127;                // 0..127
            int k   = kb * 32 + kk;
            float a = b1[k] + xs[e] * w1[k];
            if (mode != 0)
                a += xs[128 + e] * w1[128 + k] + xs[256 + e] * w1[256 + k]
                   + xs[384 + e] * w1[384 + k];
            h1s[kk * 128 + e] = tanhf(a);
            w2s[idx] = w2[kb * 4096 + idx];
        }
        __syncthreads();

        #pragma unroll 8
        for (int k = 0; k < 32; k++) {
            float4 a0 = *(const float4*)&h1s[k * 128 + tx * 8];
            float4 a1 = *(const float4*)&h1s[k * 128 + tx * 8 + 4];
            float4 c0 = *(const float4*)&w2s[k * 128 + ty * 8];
            float4 c1 = *(const float4*)&w2s[k * 128 + ty * 8 + 4];
            float av[8] = {a0.x, a0.y, a0.z, a0.w, a1.x, a1.y, a1.z, a1.w};
            float bv[8] = {c0.x, c0.y, c0.z, c0.w, c1.x, c1.y, c1.z, c1.w};
            #pragma unroll
            for (int i = 0; i < 8; i++)
                #pragma unroll
                for (int j = 0; j < 8; j++)
                    acc[i][j] = fmaf(av[i], bv[j], acc[i][j]);
        }
        __syncthreads();
    }

    // layer 3: tanh + dot with w3, partial reduce over ty groups
    #pragma unroll
    for (int i = 0; i < 8; i++) {
        float part = 0.f;
        #pragma unroll
        for (int j = 0; j < 8; j++) {
            float h2 = tanhf(acc[i][j] + b2[ty * 8 + j]);
            part = fmaf(h2, w3[ty * 8 + j], part);
        }
        red[ty * 128 + tx * 8 + i] = part;
    }
    __syncthreads();
    if (tid < 128) {
        float s = b3[0];
        #pragma unroll
        for (int t = 0; t < 16; t++) s += red[t * 128 + tid];
        int e = base + tid;
        if (mode == 0)      g_neff[e] = s;
        else if (mode == 1) g_craw[e] = s;
        else                g_kraw[e] = s;
    }
}

// ---------------- kernel 3: edge coefficients -------------------------------
__global__ __launch_bounds__(256) void coeff_kernel(const float* __restrict__ mask,
                                                    const float* __restrict__ is_center)
{
    int e = blockIdx.x * 256 + threadIdx.x;
    if (e >= NNZ) return;
    float msk = mask[e];
    float ic  = is_center[e];
    float c   = msk * 0.05f * tanhf(g_craw[e]) + ic;
    float kv  = msk * 0.10f * tanhf(g_kraw[e]);
    int   r   = e / NOFF;                 // row (center point) by construction
    g_m[e]  = KCONST * g_neff[r] * c + kv;
    g_ci[e] = 2.0f * ic - c;
}

// ---------------- kernel 4: Euler loop (8-CTA cluster, persistent) ----------
// CTA r owns rows [12r, 12r+12). smem tiles 16x100 (2-wide zero halos).
// Each thread owns 2 points; 26 coefficients per point live in registers.
// Out-of-grid taps have exactly-zero coefficients, so zero halos are correct.

__device__ __forceinline__ float2 sten13(const float* __restrict__ cf,
                                         const float2* __restrict__ buf,
                                         int s, int c)
{
    const int DI[13] = {0, 1, -1, 0, 0, 1, 1, -1, -1, 2, -2, 0, 0};
    const int DJ[13] = {0, 0, 0, 1, -1, 1, -1, 1, -1, 0, 0, 2, -2};
    float2 acc = make_float2(0.f, 0.f);
    #pragma unroll
    for (int o = 0; o < 13; o++) {
        float2 v = buf[(s + DI[o]) * 100 + (c + DJ[o])];
        acc.x = fmaf(cf[o], v.x, acc.x);
        acc.y = fmaf(cf[o], v.y, acc.y);
    }
    return acc;
}

__global__ void __cluster_dims__(8, 1, 1) __launch_bounds__(576, 1)
euler_kernel(const int* __restrict__ steps_ptr)
{
    __shared__ float2 u_s[16 * 100];
    __shared__ float2 t_s[16 * 100];

    cg::cluster_group cl = cg::this_cluster();
    int tid   = threadIdx.x;
    int rank  = blockIdx.x;
    int steps = *steps_ptr;
    float dz  = 1.5f / (float)steps;

    // init: own rows + halos straight from global U0 (out-of-grid -> 0)
    for (int idx = tid; idx < 1600; idx += 576) {
        int s = idx / 100, c = idx % 100;
        int gi = rank * 12 + s - 2;
        int gj = c - 2;
        float2 v = make_float2(0.f, 0.f);
        if (gi >= 0 && gi < NN && gj >= 0 && gj < NN) v = g_U0[gi * NN + gj];
        u_s[idx] = v;
        t_s[idx] = make_float2(0.f, 0.f);
    }

    int li0 = tid / NN;          // 0..5
    int lj  = tid % NN;          // 0..95
    int li1 = li0 + 6;           // 6..11
    int s0  = li0 + 2, s1 = li1 + 2, c = lj + 2;
    int p0  = (rank * 12 + li0) * NN + lj;
    int p1  = p0 + 6 * NN;

    float m0[13], ci0[13], m1[13], ci1[13];
    #pragma unroll
    for (int o = 0; o < 13; o++) {
        m0[o]  = g_m [p0 * NOFF + o];
        ci0[o] = g_ci[p0 * NOFF + o];
        m1[o]  = g_m [p1 * NOFF + o];
        ci1[o] = g_ci[p1 * NOFF + o];
    }

    float2* up_u = (rank > 0) ? cl.map_shared_rank(u_s, rank - 1) : (float2*)0;
    float2* up_t = (rank > 0) ? cl.map_shared_rank(t_s, rank - 1) : (float2*)0;
    float2* dn_u = (rank < 7) ? cl.map_shared_rank(u_s, rank + 1) : (float2*)0;
    float2* dn_t = (rank < 7) ? cl.map_shared_rank(t_s, rank + 1) : (float2*)0;

    bool push_up = (rank > 0) && (li0 < 2);   // local rows 0,1 -> up rank rows 14,15
    bool push_dn = (rank < 7) && (li0 >= 4);  // local rows 10,11 -> down rank rows 0,1
    int  up_off  = (li0 + 14) * 100 + c;
    int  dn_off  = (li1 - 10) * 100 + c;

    cl.sync();   // init complete cluster-wide before any DSMEM push

    for (int st = 0; st < steps; st++) {
        // t = A1 * u
        float2 t0 = sten13(m0, u_s, s0, c);
        float2 t1 = sten13(m1, u_s, s1, c);
        t_s[s0 * 100 + c] = t0;
        t_s[s1 * 100 + c] = t1;
        if (push_up) up_t[up_off] = t0;
        if (push_dn) dn_t[dn_off] = t1;
        cl.sync();

        // u += i*dz * (A2 * t)
        float2 v0 = sten13(ci0, t_s, s0, c);
        float2 v1 = sten13(ci1, t_s, s1, c);
        float2 u0 = u_s[s0 * 100 + c];
        float2 u1 = u_s[s1 * 100 + c];
        u0.x = fmaf(-dz, v0.y, u0.x); u0.y = fmaf(dz, v0.x, u0.y);
        u1.x = fmaf(-dz, v1.y, u1.x); u1.y = fmaf(dz, v1.x, u1.y);
        u_s[s0 * 100 + c] = u0;
        u_s[s1 * 100 + c] = u1;
        if (push_up) up_u[up_off] = u0;
        if (push_dn) dn_u[dn_off] = u1;
        cl.sync();
    }

    g_Uz[p0] = u_s[s0 * 100 + c];
    g_Uz[p1] = u_s[s1 * 100 + c];
}

// ---------------- kernel 5: outer-product expansion -------------------------
__global__ __launch_bounds__(256) void expand_kernel(const float* __restrict__ prof_re,
                                                     const float* __restrict__ prof_im,
                                                     float* __restrict__ out)
{
    int gid = blockIdx.x * 256 + threadIdx.x;
    if (gid >= OUTPLANE) return;
    int y = gid / OUTSIDE, x = gid - y * OUTSIDE;
    int i = y >> 3, p = y & 7;
    int j = x >> 3, q = x & 7;
    int cell = i * NN + j;
    float2 u = g_Uz[cell];
    float  e = g_Eys[cell];
    float gr = u.x * e, gi = u.y * e;
    float pr = prof_re[p * 8 + q];
    float pi = prof_im[p * 8 + q];
    out[gid]            = gr * pr - gi * pi;
    out[OUTPLANE + gid] = gr * pi + gi * pr;
}

// ---------------- launch ----------------------------------------------------
extern "C" void kernel_launch(void* const* d_in, const int* in_sizes, int n_in,
                              void* d_out, int out_size)
{
    const float* h_paras = (const float*)d_in[0];
    const float* E0      = (const float*)d_in[1];
    const float* w1n = (const float*)d_in[2];
    const float* b1n = (const float*)d_in[3];
    const float* w2n = (const float*)d_in[4];
    const float* b2n = (const float*)d_in[5];
    const float* w3n = (const float*)d_in[6];
    const float* b3n = (const float*)d_in[7];
    const float* w1c = (const float*)d_in[8];
    const float* b1c = (const float*)d_in[9];
    const float* w2c = (const float*)d_in[10];
    const float* b2c = (const float*)d_in[11];
    const float* w3c = (const float*)d_in[12];
    const float* b3c = (const float*)d_in[13];
    const float* w1k = (const float*)d_in[14];
    const float* b1k = (const float*)d_in[15];
    const float* w2k = (const float*)d_in[16];
    const float* b2k = (const float*)d_in[17];
    const float* w3k = (const float*)d_in[18];
    const float* b3k = (const float*)d_in[19];
    const float* prof_re = (const float*)d_in[20];
    const float* prof_im = (const float*)d_in[21];
    const float* dis     = (const float*)d_in[22];
    const float* mask    = (const float*)d_in[23];
    const float* is_ctr  = (const float*)d_in[24];
    const int*   coo     = (const int*)d_in[25];
    const int*   steps   = (const int*)d_in[26];
    float* out = (float*)d_out;

    prep_kernel<<<(NSQ + 255) / 256, 256>>>(h_paras, E0);
    mlp_kernel<<<NSQ / 128, 256>>>(0, w1n, b1n, w2n, b2n, w3n, b3n, dis, coo);
    mlp_kernel<<<NNZ / 128, 256>>>(1, w1c, b1c, w2c, b2c, w3c, b3c, dis, coo);
    mlp_kernel<<<NNZ / 128, 256>>>(2, w1k, b1k, w2k, b2k, w3k, b3k, dis, coo);
    coeff_kernel<<<(NNZ + 255) / 256, 256>>>(mask, is_ctr);
    euler_kernel<<<8, 576>>>(steps);
    expand_kernel<<<(OUTPLANE + 255) / 256, 256>>>(prof_re, prof_im, out);
}

// round 6
// speedup vs baseline: 1.2256x; 1.2256x over previous
#include <cuda_runtime.h>
#include <cooperative_groups.h>
#include <math.h>
#include <stdint.h>

namespace cg = cooperative_groups;

#define NN      96
#define NSQ     9216
#define NOFF    13
#define NNZ     119808
#define SIDE    816
#define BORD    24
#define KCONST  6.683942601602444f   /* 2*pi/0.94 */
#define OUTSIDE 768
#define OUTPLANE (OUTSIDE*OUTSIDE)

typedef unsigned long long u64;

// ---------------- scratch (static device globals; no allocation) ------------
__device__ float  g_hs[NSQ];
__device__ float  g_Eys[NSQ];
__device__ float  g_neff[NSQ];
__device__ float2 g_U0[NSQ];
__device__ float2 g_Uz[NSQ];
__device__ float  g_craw[NNZ];
__device__ float  g_kraw[NNZ];
__device__ float  g_m[NNZ];
__device__ float  g_ci[NNZ];

// ---------------- packed fp32x2 helpers (Blackwell) --------------------------
__device__ __forceinline__ u64 fma2(u64 a, u64 b, u64 c)
{
    u64 d;
    asm("fma.rn.f32x2 %0, %1, %2, %3;" : "=l"(d) : "l"(a), "l"(b), "l"(c));
    return d;
}
__device__ __forceinline__ u64 dup2(float x)
{
    u64 d;
    unsigned r = __float_as_uint(x);
    asm("mov.b64 %0, {%1, %1};" : "=l"(d) : "r"(r));
    return d;
}
__device__ __forceinline__ float lo32(u64 v) { return __uint_as_float((unsigned)v); }
__device__ __forceinline__ float hi32(u64 v) { return __uint_as_float((unsigned)(v >> 32)); }

// ---------------- kernel 1: hs / Eys / U0 (8x8 pooling) ---------------------
__global__ __launch_bounds__(256) void prep_kernel(const float* __restrict__ h_paras,
                                                   const float* __restrict__ E0)
{
    int p = blockIdx.x * 256 + threadIdx.x;
    if (p >= NSQ) return;
    float h  = h_paras[p];
    float s  = 1.f / (1.f + expf(-h));
    float hs = s * 0.6f + 0.2f;            // H_MIN + sig*(H_MAX-H_MIN)
    g_hs[p]  = hs;
    g_Eys[p] = 1.0f + 0.1f * tanhf(hs);
    float coupl = 0.5f + 0.5f * (1.f / (1.f + expf(-hs)));

    int i = p / NN, j = p % NN;
    const float* base = E0 + (size_t)(BORD + 8 * i) * SIDE + (BORD + 8 * j);
    float sum = 0.f;
    #pragma unroll
    for (int pi = 0; pi < 8; pi++) {
        float4 a = *(const float4*)(base + pi * SIDE);
        float4 b = *(const float4*)(base + pi * SIDE + 4);
        sum += (a.x + a.y) + (a.z + a.w) + (b.x + b.y) + (b.z + b.w);
    }
    g_U0[p] = make_float2(sum * (1.f / 64.f) * coupl, 0.f);
}

// ---------------- kernel 2: fused 3-layer MLP (mode 0=neff, 1=c, 2=k) -------
// 128 rows/block; 256 threads; 8x8 tiles via f32x2 packed FMA (pairs over rows).
__global__ __launch_bounds__(256) void mlp_kernel(int mode,
    const float* __restrict__ w1, const float* __restrict__ b1,
    const float* __restrict__ w2, const float* __restrict__ b2,
    const float* __restrict__ w3, const float* __restrict__ b3,
    const float* __restrict__ dis, const int* __restrict__ coo)
{
    __shared__ float h1s[32 * 128];
    __shared__ float w2s[32 * 128];
    __shared__ float xs[4 * 128];
    __shared__ float red[16 * 128];

    int tid  = threadIdx.x;
    int base = blockIdx.x * 128;

    if (tid < 128) {
        int e = base + tid;
        if (mode == 0) {
            xs[tid] = g_hs[e];
        } else {
            int r = coo[e];
            int c = coo[NNZ + e];
            xs[tid]       = g_hs[r];
            xs[128 + tid] = g_hs[c];
            xs[256 + tid] = dis[2 * e];
            xs[384 + tid] = dis[2 * e + 1];
        }
    }
    __syncthreads();

    int tx = tid & 15, ty = tid >> 4;
    u64 acc2[4][8];
    #pragma unroll
    for (int p = 0; p < 4; p++)
        #pragma unroll
        for (int j = 0; j < 8; j++) acc2[p][j] = 0ull;

    for (int kb = 0; kb < 4; kb++) {
        // fill h1 chunk (layer-1 + tanh) and w2 chunk
        #pragma unroll
        for (int it = 0; it < 16; it++) {
            int idx = tid + it * 256;           // 0..4095
            int kk  = idx >> 7;                 // 0..31
            int e   = idx & 127;                // 0..127
            int k   = kb * 32 + kk;
            float a = b1[k] + xs[e] * w1[k];
            if (mode != 0)
                a += xs[128 + e] * w1[128 + k] + xs[256 + e] * w1[256 + k]
                   + xs[384 + e] * w1[384 + k];
            h1s[kk * 128 + e] = tanhf(a);
            w2s[idx] = w2[kb * 4096 + idx];
        }
        __syncthreads();

        #pragma unroll 4
        for (int k = 0; k < 32; k++) {
            ulonglong2 A0 = *(const ulonglong2*)&h1s[k * 128 + tx * 8];
            ulonglong2 A1 = *(const ulonglong2*)&h1s[k * 128 + tx * 8 + 4];
            float4 c0 = *(const float4*)&w2s[k * 128 + ty * 8];
            float4 c1 = *(const float4*)&w2s[k * 128 + ty * 8 + 4];
            u64 ap[4] = {A0.x, A0.y, A1.x, A1.y};
            u64 bp[8] = {dup2(c0.x), dup2(c0.y), dup2(c0.z), dup2(c0.w),
                         dup2(c1.x), dup2(c1.y), dup2(c1.z), dup2(c1.w)};
            #pragma unroll
            for (int p = 0; p < 4; p++)
                #pragma unroll
                for (int j = 0; j < 8; j++)
                    acc2[p][j] = fma2(ap[p], bp[j], acc2[p][j]);
        }
        __syncthreads();
    }

    // layer 3: tanh + dot with w3, partial reduce over ty groups
    #pragma unroll
    for (int i = 0; i < 8; i++) {
        float part = 0.f;
        #pragma unroll
        for (int j = 0; j < 8; j++) {
            u64 v = acc2[i >> 1][j];
            float pre = ((i & 1) ? hi32(v) : lo32(v)) + b2[ty * 8 + j];
            float h2 = tanhf(pre);
            part = fmaf(h2, w3[ty * 8 + j], part);
        }
        red[ty * 128 + tx * 8 + i] = part;
    }
    __syncthreads();
    if (tid < 128) {
        float s = b3[0];
        #pragma unroll
        for (int t = 0; t < 16; t++) s += red[t * 128 + tid];
        int e = base + tid;
        if (mode == 0)      g_neff[e] = s;
        else if (mode == 1) g_craw[e] = s;
        else                g_kraw[e] = s;
    }
}

// ---------------- kernel 3: edge coefficients -------------------------------
__global__ __launch_bounds__(256) void coeff_kernel(const float* __restrict__ mask,
                                                    const float* __restrict__ is_center)
{
    int e = blockIdx.x * 256 + threadIdx.x;
    if (e >= NNZ) return;
    float msk = mask[e];
    float ic  = is_center[e];
    float c   = msk * 0.05f * tanhf(g_craw[e]) + ic;
    float kv  = msk * 0.10f * tanhf(g_kraw[e]);
    int   r   = e / NOFF;                 // row (center point) by construction
    g_m[e]  = KCONST * g_neff[r] * c + kv;
    g_ci[e] = 2.0f * ic - c;
}

// ---------------- kernel 4: Euler loop --------------------------------------
// Out-of-grid taps have exactly-zero coefficients, so zero halos are correct.

__device__ __forceinline__ float2 sten13(const float* __restrict__ cf,
                                         const float2* __restrict__ buf,
                                         int s, int c)
{
    const int DI[13] = {0, 1, -1, 0, 0, 1, 1, -1, -1, 2, -2, 0, 0};
    const int DJ[13] = {0, 0, 0, 1, -1, 1, -1, 1, -1, 0, 0, 2, -2};
    float2 acc = make_float2(0.f, 0.f);
    #pragma unroll
    for (int o = 0; o < 13; o++) {
        float2 v = buf[(s + DI[o]) * 100 + (c + DJ[o])];
        acc.x = fmaf(cf[o], v.x, acc.x);
        acc.y = fmaf(cf[o], v.y, acc.y);
    }
    return acc;
}

// --- 16-CTA cluster version: 6 rows/CTA, 1 point/thread, tiles 10x100 -------
__global__ void __launch_bounds__(576, 1)
euler16_kernel(const int* __restrict__ steps_ptr)
{
    __shared__ float2 u_s[10 * 100];
    __shared__ float2 t_s[10 * 100];

    cg::cluster_group cl = cg::this_cluster();
    int tid   = threadIdx.x;
    int rank  = blockIdx.x;
    int steps = *steps_ptr;
    float dz  = 1.5f / (float)steps;

    for (int idx = tid; idx < 1000; idx += 576) {
        int s = idx / 100, c = idx % 100;
        int gi = rank * 6 + s - 2;
        int gj = c - 2;
        float2 v = make_float2(0.f, 0.f);
        if (gi >= 0 && gi < NN && gj >= 0 && gj < NN) v = g_U0[gi * NN + gj];
        u_s[idx] = v;
        t_s[idx] = make_float2(0.f, 0.f);
    }

    int li = tid / NN;           // 0..5
    int lj = tid % NN;           // 0..95
    int s  = li + 2, c = lj + 2;
    int p  = (rank * 6 + li) * NN + lj;

    float m[13], ci[13];
    #pragma unroll
    for (int o = 0; o < 13; o++) {
        m[o]  = g_m [p * NOFF + o];
        ci[o] = g_ci[p * NOFF + o];
    }

    float2* up_u = (rank > 0)  ? cl.map_shared_rank(u_s, rank - 1) : (float2*)0;
    float2* up_t = (rank > 0)  ? cl.map_shared_rank(t_s, rank - 1) : (float2*)0;
    float2* dn_u = (rank < 15) ? cl.map_shared_rank(u_s, rank + 1) : (float2*)0;
    float2* dn_t = (rank < 15) ? cl.map_shared_rank(t_s, rank + 1) : (float2*)0;

    bool push_up = (rank > 0)  && (li < 2);   // local rows 0,1 -> up rank rows 8,9
    bool push_dn = (rank < 15) && (li >= 4);  // local rows 4,5 -> down rank rows 0,1
    int  up_off  = (li + 8) * 100 + c;
    int  dn_off  = (li - 4) * 100 + c;

    cl.sync();

    for (int st = 0; st < steps; st++) {
        float2 t0 = sten13(m, u_s, s, c);
        t_s[s * 100 + c] = t0;
        if (push_up) up_t[up_off] = t0;
        if (push_dn) dn_t[dn_off] = t0;
        cl.sync();

        float2 v0 = sten13(ci, t_s, s, c);
        float2 u0 = u_s[s * 100 + c];
        u0.x = fmaf(-dz, v0.y, u0.x);
        u0.y = fmaf( dz, v0.x, u0.y);
        u_s[s * 100 + c] = u0;
        if (push_up) up_u[up_off] = u0;
        if (push_dn) dn_u[dn_off] = u0;
        cl.sync();
    }

    g_Uz[p] = u_s[s * 100 + c];
}

// --- 8-CTA fallback (proven in round 4): 12 rows/CTA, 2 points/thread -------
__global__ void __cluster_dims__(8, 1, 1) __launch_bounds__(576, 1)
euler8_kernel(const int* __restrict__ steps_ptr)
{
    __shared__ float2 u_s[16 * 100];
    __shared__ float2 t_s[16 * 100];

    cg::cluster_group cl = cg::this_cluster();
    int tid   = threadIdx.x;
    int rank  = blockIdx.x;
    int steps = *steps_ptr;
    float dz  = 1.5f / (float)steps;

    for (int idx = tid; idx < 1600; idx += 576) {
        int s = idx / 100, c = idx % 100;
        int gi = rank * 12 + s - 2;
        int gj = c - 2;
        float2 v = make_float2(0.f, 0.f);
        if (gi >= 0 && gi < NN && gj >= 0 && gj < NN) v = g_U0[gi * NN + gj];
        u_s[idx] = v;
        t_s[idx] = make_float2(0.f, 0.f);
    }

    int li0 = tid / NN, lj = tid % NN;
    int li1 = li0 + 6;
    int s0  = li0 + 2, s1 = li1 + 2, c = lj + 2;
    int p0  = (rank * 12 + li0) * NN + lj;
    int p1  = p0 + 6 * NN;

    float m0[13], ci0[13], m1[13], ci1[13];
    #pragma unroll
    for (int o = 0; o < 13; o++) {
        m0[o]  = g_m [p0 * NOFF + o];
        ci0[o] = g_ci[p0 * NOFF + o];
        m1[o]  = g_m [p1 * NOFF + o];
        ci1[o] = g_ci[p1 * NOFF + o];
    }

    float2* up_u = (rank > 0) ? cl.map_shared_rank(u_s, rank - 1) : (float2*)0;
    float2* up_t = (rank > 0) ? cl.map_shared_rank(t_s, rank - 1) : (float2*)0;
    float2* dn_u = (rank < 7) ? cl.map_shared_rank(u_s, rank + 1) : (float2*)0;
    float2* dn_t = (rank < 7) ? cl.map_shared_rank(t_s, rank + 1) : (float2*)0;

    bool push_up = (rank > 0) && (li0 < 2);
    bool push_dn = (rank < 7) && (li0 >= 4);
    int  up_off  = (li0 + 14) * 100 + c;
    int  dn_off  = (li1 - 10) * 100 + c;

    cl.sync();

    for (int st = 0; st < steps; st++) {
        float2 t0 = sten13(m0, u_s, s0, c);
        float2 t1 = sten13(m1, u_s, s1, c);
        t_s[s0 * 100 + c] = t0;
        t_s[s1 * 100 + c] = t1;
        if (push_up) up_t[up_off] = t0;
        if (push_dn) dn_t[dn_off] = t1;
        cl.sync();

        float2 v0 = sten13(ci0, t_s, s0, c);
        float2 v1 = sten13(ci1, t_s, s1, c);
        float2 u0 = u_s[s0 * 100 + c];
        float2 u1 = u_s[s1 * 100 + c];
        u0.x = fmaf(-dz, v0.y, u0.x); u0.y = fmaf(dz, v0.x, u0.y);
        u1.x = fmaf(-dz, v1.y, u1.x); u1.y = fmaf(dz, v1.x, u1.y);
        u_s[s0 * 100 + c] = u0;
        u_s[s1 * 100 + c] = u1;
        if (push_up) up_u[up_off] = u0;
        if (push_dn) dn_u[dn_off] = u1;
        cl.sync();
    }

    g_Uz[p0] = u_s[s0 * 100 + c];
    g_Uz[p1] = u_s[s1 * 100 + c];
}

// ---------------- kernel 5: outer-product expansion -------------------------
__global__ __launch_bounds__(256) void expand_kernel(const float* __restrict__ prof_re,
                                                     const float* __restrict__ prof_im,
                                                     float* __restrict__ out)
{
    int gid = blockIdx.x * 256 + threadIdx.x;
    if (gid >= OUTPLANE) return;
    int y = gid / OUTSIDE, x = gid - y * OUTSIDE;
    int i = y >> 3, p = y & 7;
    int j = x >> 3, q = x & 7;
    int cell = i * NN + j;
    float2 u = g_Uz[cell];
    float  e = g_Eys[cell];
    float gr = u.x * e, gi = u.y * e;
    float pr = prof_re[p * 8 + q];
    float pi = prof_im[p * 8 + q];
    out[gid]            = gr * pr - gi * pi;
    out[OUTPLANE + gid] = gr * pi + gi * pr;
}

// ---------------- launch ----------------------------------------------------
extern "C" void kernel_launch(void* const* d_in, const int* in_sizes, int n_in,
                              void* d_out, int out_size)
{
    const float* h_paras = (const float*)d_in[0];
    const float* E0      = (const float*)d_in[1];
    const float* w1n = (const float*)d_in[2];
    const float* b1n = (const float*)d_in[3];
    const float* w2n = (const float*)d_in[4];
    const float* b2n = (const float*)d_in[5];
    const float* w3n = (const float*)d_in[6];
    const float* b3n = (const float*)d_in[7];
    const float* w1c = (const float*)d_in[8];
    const float* b1c = (const float*)d_in[9];
    const float* w2c = (const float*)d_in[10];
    const float* b2c = (const float*)d_in[11];
    const float* w3c = (const float*)d_in[12];
    const float* b3c = (const float*)d_in[13];
    const float* w1k = (const float*)d_in[14];
    const float* b1k = (const float*)d_in[15];
    const float* w2k = (const float*)d_in[16];
    const float* b2k = (const float*)d_in[17];
    const float* w3k = (const float*)d_in[18];
    const float* b3k = (const float*)d_in[19];
    const float* prof_re = (const float*)d_in[20];
    const float* prof_im = (const float*)d_in[21];
    const float* dis     = (const float*)d_in[22];
    const float* mask    = (const float*)d_in[23];
    const float* is_ctr  = (const float*)d_in[24];
    const int*   coo     = (const int*)d_in[25];
    const int*   steps   = (const int*)d_in[26];
    float* out = (float*)d_out;

    prep_kernel<<<(NSQ + 255) / 256, 256>>>(h_paras, E0);
    mlp_kernel<<<NSQ / 128, 256>>>(0, w1n, b1n, w2n, b2n, w3n, b3n, dis, coo);
    mlp_kernel<<<NNZ / 128, 256>>>(1, w1c, b1c, w2c, b2c, w3c, b3c, dis, coo);
    mlp_kernel<<<NNZ / 128, 256>>>(2, w1k, b1k, w2k, b2k, w3k, b3k, dis, coo);
    coeff_kernel<<<(NNZ + 255) / 256, 256>>>(mask, is_ctr);

    // Euler: try 16-CTA cluster (nonportable), deterministic fallback to 8-CTA.
    cudaError_t err = cudaFuncSetAttribute(
        euler16_kernel, cudaFuncAttributeNonPortableClusterSizeAllowed, 1);
    if (err == cudaSuccess) {
        cudaLaunchConfig_t cfg = {};
        cfg.gridDim  = dim3(16, 1, 1);
        cfg.blockDim = dim3(576, 1, 1);
        cfg.dynamicSmemBytes = 0;
        cfg.stream = 0;
        cudaLaunchAttribute attrs[1];
        attrs[0].id = cudaLaunchAttributeClusterDimension;
        attrs[0].val.clusterDim.x = 16;
        attrs[0].val.clusterDim.y = 1;
        attrs[0].val.clusterDim.z = 1;
        cfg.attrs = attrs;
        cfg.numAttrs = 1;
        err = cudaLaunchKernelEx(&cfg, euler16_kernel, steps);
    }
    if (err != cudaSuccess) {
        cudaGetLastError();   // clear sticky state from the failed attempt
        euler8_kernel<<<8, 576>>>(steps);
    }

    expand_kernel<<<(OUTPLANE + 255) / 256, 256>>>(prof_re, prof_im, out);
}